// round 17
// baseline (speedup 1.0000x reference)
#include <cuda_runtime.h>
#include <cstdint>

#define B_SZ 64
#define T_SZ 2048
#define I_SZ 256
#define H_SZ 256
#define O_SZ 128
#define M_SZ (B_SZ * T_SZ)   // 131072 rows

// Scratch (device globals: no allocations allowed)
__device__ float g_xp1 [(size_t)M_SZ * H_SZ];        // 128 MB
__device__ float g_xp2s[4 * (size_t)M_SZ * O_SZ];    // 256 MB: 4 partial streams

// ---------------------------------------------------------------------------
union f2u { float2 f; unsigned long long u; };

__device__ __forceinline__ float2 ffma2(float2 a, float2 b, float2 c) {
    f2u A, Bv, C;
    A.f = a; Bv.f = b; C.f = c;
    asm("fma.rn.f32x2 %0, %1, %2, %3;"
        : "=l"(C.u) : "l"(A.u), "l"(Bv.u), "l"(C.u));
    return C.f;
}

// Branch-free fast tanh (validated: rel_err 4.4e-7 vs 1e-3 budget)
__device__ __forceinline__ float fast_tanh(float x) {
    float ax = fabsf(x);
    float e  = __expf(-2.0f * ax);
    float t  = __fdividef(1.0f - e, 1.0f + e);
    return copysignf(t, x);
}

__device__ __forceinline__ uint32_t smem_u32(const void* p) {
    return (uint32_t)__cvta_generic_to_shared(p);
}
__device__ __forceinline__ uint32_t mapa_peer(uint32_t a, unsigned peer) {
    uint32_t r;
    asm("mapa.shared::cluster.u32 %0, %1, %2;" : "=r"(r) : "r"(a), "r"(peer));
    return r;
}
__device__ __forceinline__ void mbar_wait_acq_cluster(uint32_t mbar, uint32_t parity) {
    asm volatile(
        "{\n\t.reg .pred P;\n\t"
        "W_%=:\n\t"
        "mbarrier.try_wait.parity.acquire.cluster.shared::cta.b64 P, [%0], %1;\n\t"
        "@!P bra W_%=;\n\t}"
        :: "r"(mbar), "r"(parity) : "memory");
}

// ---------------------------------------------------------------------------
// SGEMM, double-buffered + conflict-free B reads (R15 champion, frozen)
// ---------------------------------------------------------------------------
__global__ __launch_bounds__(256, 2)
void sgemm_bias_kernel(const float* __restrict__ A,
                       const float* __restrict__ W,
                       const float* __restrict__ bias_a,
                       const float* __restrict__ bias_b,
                       float* __restrict__ C, int K, int N)
{
    constexpr int BM = 128, BN = 128, BK = 16;
    __shared__ float As[2][BK][BM];
    __shared__ float Bs[2][BK][BN];

    int tid = threadIdx.x;
    int bm = blockIdx.y * BM;
    int bn = blockIdx.x * BN;
    int tm = tid >> 4;
    int tn = tid & 15;

    int lrow0 = (tid * 2)     >> 2, lc40 = (tid * 2)     & 3;
    int lrow1 = (tid * 2 + 1) >> 2, lc41 = (tid * 2 + 1) & 3;

    float2 acc[8][4];
    #pragma unroll
    for (int i = 0; i < 8; i++)
        #pragma unroll
        for (int j = 0; j < 4; j++) acc[i][j] = make_float2(0.f, 0.f);

    const float* Ab = A + (size_t)bm * K;
    const float* Wb = W + (size_t)bn * K;

    float4 va0, va1, vb0, vb1;

    va0 = *(const float4*)(Ab + (size_t)lrow0 * K + 0 + lc40 * 4);
    va1 = *(const float4*)(Ab + (size_t)lrow1 * K + 0 + lc41 * 4);
    vb0 = *(const float4*)(Wb + (size_t)lrow0 * K + 0 + lc40 * 4);
    vb1 = *(const float4*)(Wb + (size_t)lrow1 * K + 0 + lc41 * 4);
    As[0][lc40 * 4 + 0][lrow0] = va0.x; As[0][lc40 * 4 + 1][lrow0] = va0.y;
    As[0][lc40 * 4 + 2][lrow0] = va0.z; As[0][lc40 * 4 + 3][lrow0] = va0.w;
    As[0][lc41 * 4 + 0][lrow1] = va1.x; As[0][lc41 * 4 + 1][lrow1] = va1.y;
    As[0][lc41 * 4 + 2][lrow1] = va1.z; As[0][lc41 * 4 + 3][lrow1] = va1.w;
    Bs[0][lc40 * 4 + 0][lrow0] = vb0.x; Bs[0][lc40 * 4 + 1][lrow0] = vb0.y;
    Bs[0][lc40 * 4 + 2][lrow0] = vb0.z; Bs[0][lc40 * 4 + 3][lrow0] = vb0.w;
    Bs[0][lc41 * 4 + 0][lrow1] = vb1.x; Bs[0][lc41 * 4 + 1][lrow1] = vb1.y;
    Bs[0][lc41 * 4 + 2][lrow1] = vb1.z; Bs[0][lc41 * 4 + 3][lrow1] = vb1.w;
    __syncthreads();

    int buf = 0;
    for (int kt = 0; kt < K; kt += BK) {
        int ktn = kt + BK;
        bool more = (ktn < K);
        if (more) {
            va0 = *(const float4*)(Ab + (size_t)lrow0 * K + ktn + lc40 * 4);
            va1 = *(const float4*)(Ab + (size_t)lrow1 * K + ktn + lc41 * 4);
            vb0 = *(const float4*)(Wb + (size_t)lrow0 * K + ktn + lc40 * 4);
            vb1 = *(const float4*)(Wb + (size_t)lrow1 * K + ktn + lc41 * 4);
        }

        #pragma unroll
        for (int kk = 0; kk < BK; kk++) {
            float4 a0 = *(const float4*)&As[buf][kk][tm * 8];
            float4 a1 = *(const float4*)&As[buf][kk][tm * 8 + 4];
            float4 b0 = *(const float4*)&Bs[buf][kk][tn * 4];
            float4 b1 = *(const float4*)&Bs[buf][kk][64 + tn * 4];
            float av[8] = {a0.x, a0.y, a0.z, a0.w, a1.x, a1.y, a1.z, a1.w};
            float2 bv[4] = {make_float2(b0.x, b0.y), make_float2(b0.z, b0.w),
                            make_float2(b1.x, b1.y), make_float2(b1.z, b1.w)};
            #pragma unroll
            for (int i = 0; i < 8; i++) {
                float2 ai = make_float2(av[i], av[i]);
                #pragma unroll
                for (int j = 0; j < 4; j++)
                    acc[i][j] = ffma2(ai, bv[j], acc[i][j]);
            }
        }

        if (more) {
            int nb = buf ^ 1;
            As[nb][lc40 * 4 + 0][lrow0] = va0.x; As[nb][lc40 * 4 + 1][lrow0] = va0.y;
            As[nb][lc40 * 4 + 2][lrow0] = va0.z; As[nb][lc40 * 4 + 3][lrow0] = va0.w;
            As[nb][lc41 * 4 + 0][lrow1] = va1.x; As[nb][lc41 * 4 + 1][lrow1] = va1.y;
            As[nb][lc41 * 4 + 2][lrow1] = va1.z; As[nb][lc41 * 4 + 3][lrow1] = va1.w;
            Bs[nb][lc40 * 4 + 0][lrow0] = vb0.x; Bs[nb][lc40 * 4 + 1][lrow0] = vb0.y;
            Bs[nb][lc40 * 4 + 2][lrow0] = vb0.z; Bs[nb][lc40 * 4 + 3][lrow0] = vb0.w;
            Bs[nb][lc41 * 4 + 0][lrow1] = vb1.x; Bs[nb][lc41 * 4 + 1][lrow1] = vb1.y;
            Bs[nb][lc41 * 4 + 2][lrow1] = vb1.z; Bs[nb][lc41 * 4 + 3][lrow1] = vb1.w;
            __syncthreads();
            buf = nb;
        }
    }

    float2 bb[4];
    #pragma unroll
    for (int j = 0; j < 2; j++) {
        int n = bn + tn * 4 + j * 2;
        bb[j] = make_float2(bias_a[n] + bias_b[n], bias_a[n + 1] + bias_b[n + 1]);
    }
    #pragma unroll
    for (int j = 0; j < 2; j++) {
        int n = bn + 64 + tn * 4 + j * 2;
        bb[2 + j] = make_float2(bias_a[n] + bias_b[n], bias_a[n + 1] + bias_b[n + 1]);
    }
    #pragma unroll
    for (int i = 0; i < 8; i++) {
        int m = bm + tm * 8 + i;
        float* Crow0 = C + (size_t)m * N + bn + tn * 4;
        float* Crow1 = C + (size_t)m * N + bn + 64 + tn * 4;
        #pragma unroll
        for (int j = 0; j < 2; j++) {
            float2 v = make_float2(acc[i][j].x + bb[j].x, acc[i][j].y + bb[j].y);
            *(float2*)(Crow0 + j * 2) = v;
        }
        #pragma unroll
        for (int j = 0; j < 2; j++) {
            float2 v = make_float2(acc[i][2 + j].x + bb[2 + j].x,
                                   acc[i][2 + j].y + bb[2 + j].y);
            *(float2*)(Crow1 + j * 2) = v;
        }
    }
}

// ---------------------------------------------------------------------------
// Layer-1 scan (R10 psum-exchange champion) + inline QUARTER-GEMV for xp2:
// every thread handles output j=tid&127, input quarter q=tid>>7 (64 of my
// CTA's 128 local h values; 32 f2 weights = 64 regs). In the idle window
// between psum-send and mbar-wait it computes the quarter-dot of h1[t-1]
// (= hbuf[p], sync-stable) -> stream 2r+q of g_xp2s. Post-loop covers t=T-1.
// GEMM2 and the h1 buffer are deleted.
// ---------------------------------------------------------------------------
__global__ void __cluster_dims__(2, 1, 1) __launch_bounds__(256, 1)
rnn_scan1_kernel(const float* __restrict__ W_hh,
                 const float* __restrict__ W_ih2,
                 const float* __restrict__ xp,
                 float* __restrict__ xp2s)
{
    __shared__ alignas(16) float hbuf[2][128];   // local h half, double-buffered
    __shared__ alignas(16) float pbuf[2][128];   // peer psums for my outputs
    __shared__ alignas(8) unsigned long long mbar;

    int tid = threadIdx.x;      // == global output index o (0..255)
    unsigned r;
    asm("mov.u32 %0, %%cluster_ctarank;" : "=r"(r));
    int b = blockIdx.x >> 1;
    unsigned peer = r ^ 1u;

    bool owner  = ((unsigned)(tid >> 7) == r);   // my output is in my half
    int  m      = tid & 127;                     // index within a half
    int  q      = tid >> 7;                      // GEMV input quarter (warp-uniform)

    // Scan weights: W_hh[o][r*128 .. r*128+127]  (my input half, all outputs)
    float2 w2[64];
    {
        const float4* wp = (const float4*)(W_hh + (size_t)tid * H_SZ + (int)r * 128);
        #pragma unroll
        for (int j = 0; j < 32; j++) {
            float4 v = wp[j];
            w2[2 * j]     = make_float2(v.x, v.y);
            w2[2 * j + 1] = make_float2(v.z, v.w);
        }
    }

    // GEMV weights: W_ih2[m][r*128 + q*64 .. +63]  (64 floats = 32 f2)
    float2 wg[32];
    {
        const float4* gp = (const float4*)(W_ih2 + (size_t)m * H_SZ + (int)r * 128 + q * 64);
        #pragma unroll
        for (int k = 0; k < 16; k++) {
            float4 v = gp[k];
            wg[2 * k]     = make_float2(v.x, v.y);
            wg[2 * k + 1] = make_float2(v.z, v.w);
        }
    }
    // Output stream: 2r+q, element [b][t][m]
    float* xp2out = xp2s + ((size_t)(2 * (int)r + q)) * ((size_t)M_SZ * O_SZ)
                  + (size_t)b * T_SZ * O_SZ + m;

    if (tid < 128) hbuf[0][tid] = 0.f;           // h0 = 0 (local half)

    uint32_t mb = smem_u32(&mbar);
    if (tid == 0)   // 128 arrivals per phase (one per sending lane)
        asm volatile("mbarrier.init.shared.b64 [%0], %1;" :: "r"(mb), "r"(128) : "memory");

    uint32_t rp0 = mapa_peer(smem_u32(&pbuf[0][m]), peer);
    uint32_t rp1 = mapa_peer(smem_u32(&pbuf[1][m]), peer);
    uint32_t rmb = mapa_peer(mb, peer);

    const float* xpb = xp + (size_t)b * T_SZ * H_SZ + tid;

    float pf[4];
    #pragma unroll
    for (int i = 0; i < 4; i++)
        pf[i] = __ldg(xpb + (size_t)i * H_SZ);

    // mbar + h0 visible cluster-wide before any remote traffic
    asm volatile("barrier.cluster.arrive.aligned;\n\tbarrier.cluster.wait.aligned;" ::: "memory");

    int p = 0;
    #pragma unroll 2
    for (int t = 0; t < T_SZ; t++) {
        float xv = pf[t & 3];
        int tn4 = (t + 4 < T_SZ) ? (t + 4) : (T_SZ - 1);
        pf[t & 3] = __ldg(xpb + (size_t)tn4 * H_SZ);

        // psum over LOCAL h half (warp-broadcast float4 reads, conflict-free)
        const float4* hb = (const float4*)&hbuf[p][0];
        float2 a0 = make_float2(0.f, 0.f), a1 = a0, a2 = a0, a3 = a0;
        #pragma unroll
        for (int j = 0; j < 8; j++) {
            float4 h0 = hb[4 * j];
            float4 h1v = hb[4 * j + 1];
            float4 h2 = hb[4 * j + 2];
            float4 h3 = hb[4 * j + 3];
            a0 = ffma2(make_float2(h0.x,  h0.y),  w2[8 * j],     a0);
            a1 = ffma2(make_float2(h0.z,  h0.w),  w2[8 * j + 1], a1);
            a2 = ffma2(make_float2(h1v.x, h1v.y), w2[8 * j + 2], a2);
            a3 = ffma2(make_float2(h1v.z, h1v.w), w2[8 * j + 3], a3);
            a0 = ffma2(make_float2(h2.x,  h2.y),  w2[8 * j + 4], a0);
            a1 = ffma2(make_float2(h2.z,  h2.w),  w2[8 * j + 5], a1);
            a2 = ffma2(make_float2(h3.x,  h3.y),  w2[8 * j + 6], a2);
            a3 = ffma2(make_float2(h3.z,  h3.w),  w2[8 * j + 7], a3);
        }
        float s = (a0.x + a1.x) + (a2.x + a3.x) + (a0.y + a1.y) + (a2.y + a3.y);

        if (!owner) {
            // ship psum to the peer (its output) + arrive; release orders store
            uint32_t ra = p ? rp1 : rp0;
            asm volatile("st.shared::cluster.f32 [%0], %1;" :: "r"(ra), "f"(s) : "memory");
            asm volatile("mbarrier.arrive.release.cluster.shared::cluster.b64 _, [%0];"
                         :: "r"(rmb) : "memory");
        }

        // ---- inline quarter-GEMV of h1[t-1] (hbuf[p]) in the idle window ----
        if (t > 0) {
            const float4* hq = hb + q * 16;            // my 64-input quarter
            float2 g0 = make_float2(0.f, 0.f), g1 = g0, g2 = g0, g3 = g0;
            #pragma unroll
            for (int j = 0; j < 8; j++) {
                float4 h0 = hq[2 * j];
                float4 h1v = hq[2 * j + 1];
                g0 = ffma2(make_float2(h0.x,  h0.y),  wg[4 * j],     g0);
                g1 = ffma2(make_float2(h0.z,  h0.w),  wg[4 * j + 1], g1);
                g2 = ffma2(make_float2(h1v.x, h1v.y), wg[4 * j + 2], g2);
                g3 = ffma2(make_float2(h1v.z, h1v.w), wg[4 * j + 3], g3);
            }
            float xg = (g0.x + g1.x) + (g2.x + g3.x) + (g0.y + g1.y) + (g2.y + g3.y);
            xp2out[(size_t)(t - 1) * O_SZ] = xg;
        }

        // late wait: peer psums for THIS step (phase p)
        mbar_wait_acq_cluster(mb, (uint32_t)p);

        if (owner) {
            float v = fast_tanh(s + pbuf[p][m] + xv);
            hbuf[p ^ 1][m] = v;                    // local h half for step t+1
        }
        __syncthreads();                           // step separator
        p ^= 1;
    }

    // final quarter-GEMV for h1[T-1] (in hbuf[p] after the loop)
    {
        const float4* hq = (const float4*)&hbuf[p][0] + q * 16;
        float2 g0 = make_float2(0.f, 0.f), g1 = g0, g2 = g0, g3 = g0;
        #pragma unroll
        for (int j = 0; j < 8; j++) {
            float4 h0 = hq[2 * j];
            float4 h1v = hq[2 * j + 1];
            g0 = ffma2(make_float2(h0.x,  h0.y),  wg[4 * j],     g0);
            g1 = ffma2(make_float2(h0.z,  h0.w),  wg[4 * j + 1], g1);
            g2 = ffma2(make_float2(h1v.x, h1v.y), wg[4 * j + 2], g2);
            g3 = ffma2(make_float2(h1v.z, h1v.w), wg[4 * j + 3], g3);
        }
        float xg = (g0.x + g1.x) + (g2.x + g3.x) + (g0.y + g1.y) + (g2.y + g3.y);
        xp2out[(size_t)(T_SZ - 1) * O_SZ] = xg;
    }

    asm volatile("barrier.cluster.arrive.aligned;\n\tbarrier.cluster.wait.aligned;" ::: "memory");
}

// ---------------------------------------------------------------------------
// Layer-2 scan (R9 champion + 4-stream xp2 and bias): 128 threads/CTA,
// thread == output, no reduction, one STS + one STG per step.
// ---------------------------------------------------------------------------
__global__ __launch_bounds__(128, 1)
void rnn_scan2_kernel(const float* __restrict__ W_hh,
                      const float* __restrict__ xp2s,
                      const float* __restrict__ b_ih2,
                      const float* __restrict__ b_hh2,
                      float* __restrict__ out)
{
    __shared__ float obuf[2][O_SZ];

    int tid = threadIdx.x;      // == output index o
    int b = blockIdx.x;

    float2 w2[64];
    {
        const float4* wp = (const float4*)(W_hh + (size_t)tid * O_SZ);
        #pragma unroll
        for (int j = 0; j < 32; j++) {
            float4 v = wp[j];
            w2[2 * j]     = make_float2(v.x, v.y);
            w2[2 * j + 1] = make_float2(v.z, v.w);
        }
    }
    float bias_o = b_ih2[tid] + b_hh2[tid];

    obuf[0][tid] = 0.f;

    const size_t SSTR = (size_t)M_SZ * O_SZ;
    const float* x0 = xp2s + 0 * SSTR + (size_t)b * T_SZ * O_SZ + tid;
    const float* x1 = xp2s + 1 * SSTR + (size_t)b * T_SZ * O_SZ + tid;
    const float* x2 = xp2s + 2 * SSTR + (size_t)b * T_SZ * O_SZ + tid;
    const float* x3 = xp2s + 3 * SSTR + (size_t)b * T_SZ * O_SZ + tid;
    float* ob = out + (size_t)b * T_SZ * O_SZ + tid;

    float pf0[4], pf1[4], pf2[4], pf3[4];
    #pragma unroll
    for (int i = 0; i < 4; i++) {
        pf0[i] = __ldg(x0 + (size_t)i * O_SZ);
        pf1[i] = __ldg(x1 + (size_t)i * O_SZ);
        pf2[i] = __ldg(x2 + (size_t)i * O_SZ);
        pf3[i] = __ldg(x3 + (size_t)i * O_SZ);
    }

    __syncthreads();

    int p = 0;
    #pragma unroll 2
    for (int t = 0; t < T_SZ; t++) {
        float xv = (pf0[t & 3] + pf1[t & 3]) + (pf2[t & 3] + pf3[t & 3]) + bias_o;
        int tn4 = (t + 4 < T_SZ) ? (t + 4) : (T_SZ - 1);
        pf0[t & 3] = __ldg(x0 + (size_t)tn4 * O_SZ);
        pf1[t & 3] = __ldg(x1 + (size_t)tn4 * O_SZ);
        pf2[t & 3] = __ldg(x2 + (size_t)tn4 * O_SZ);
        pf3[t & 3] = __ldg(x3 + (size_t)tn4 * O_SZ);

        const float4* hb = (const float4*)&obuf[p][0];     // warp-broadcast reads
        float2 a0 = make_float2(0.f, 0.f), a1 = a0, a2 = a0, a3 = a0;
        #pragma unroll
        for (int j = 0; j < 8; j++) {
            float4 h0 = hb[4 * j];
            float4 h1v = hb[4 * j + 1];
            float4 h2 = hb[4 * j + 2];
            float4 h3 = hb[4 * j + 3];
            a0 = ffma2(make_float2(h0.x,  h0.y),  w2[8 * j],     a0);
            a1 = ffma2(make_float2(h0.z,  h0.w),  w2[8 * j + 1], a1);
            a2 = ffma2(make_float2(h1v.x, h1v.y), w2[8 * j + 2], a2);
            a3 = ffma2(make_float2(h1v.z, h1v.w), w2[8 * j + 3], a3);
            a0 = ffma2(make_float2(h2.x,  h2.y),  w2[8 * j + 4], a0);
            a1 = ffma2(make_float2(h2.z,  h2.w),  w2[8 * j + 5], a1);
            a2 = ffma2(make_float2(h3.x,  h3.y),  w2[8 * j + 6], a2);
            a3 = ffma2(make_float2(h3.z,  h3.w),  w2[8 * j + 7], a3);
        }
        float s = (a0.x + a1.x) + (a2.x + a3.x) + (a0.y + a1.y) + (a2.y + a3.y);

        float v = fast_tanh(s + xv);                       // no reduction needed
        obuf[p ^ 1][tid] = v;                              // ONE STS
        ob[(size_t)t * O_SZ] = v;                          // ONE STG
        __syncthreads();
        p ^= 1;
    }
}

// ---------------------------------------------------------------------------
extern "C" void kernel_launch(void* const* d_in, const int* in_sizes, int n_in,
                              void* d_out, int out_size)
{
    const float* x     = (const float*)d_in[0];
    const float* W_ih1 = (const float*)d_in[1];
    const float* W_hh1 = (const float*)d_in[2];
    const float* b_ih1 = (const float*)d_in[3];
    const float* b_hh1 = (const float*)d_in[4];
    const float* W_ih2 = (const float*)d_in[5];
    const float* W_hh2 = (const float*)d_in[6];
    const float* b_ih2 = (const float*)d_in[7];
    const float* b_hh2 = (const float*)d_in[8];
    float* out = (float*)d_out;

    float *xp1, *xp2s;
    cudaGetSymbolAddress((void**)&xp1,  g_xp1);
    cudaGetSymbolAddress((void**)&xp2s, g_xp2s);

    // Phase 1: xp1 = x @ W_ih1^T + (b_ih1 + b_hh1)   [131072 x 256]
    dim3 g1(H_SZ / 128, M_SZ / 128);
    sgemm_bias_kernel<<<g1, 256>>>(x, W_ih1, b_ih1, b_hh1, xp1, I_SZ, H_SZ);

    // Phase 2: layer-1 scan with INLINE xp2 quarter-GEMVs (GEMM2 deleted)
    rnn_scan1_kernel<<<B_SZ * 2, 256>>>(W_hh1, W_ih2, xp1, xp2s);

    // Phase 3: layer-2 scan, consumes 4 xp2 streams + bias, writes output
    rnn_scan2_kernel<<<B_SZ, 128>>>(W_hh2, xp2s, b_ih2, b_hh2, out);
}